// round 16
// baseline (speedup 1.0000x reference)
#include <cuda_runtime.h>
#include <cuda_fp16.h>
#include <math.h>
#include <stdint.h>

// Shapes: B=2, C=256, H=W=64 -> HW=4096, DQ=16, x has 2C=512 channels.
#define HW 4096
#define CCH 256
#define PSTRH 72   // P smem row stride (halves): banks 4r+c, conflict-free
#define USTRH 72   // U smem row stride (halves)
#define EOFF 8.0f  // uniform logit offset (cancels in O/l)
#define USZB (256 * USTRH * 2)   // one U buffer, bytes (36864)
#define PSZB (128 * PSTRH * 2)   // one P buffer, bytes (18432)
#define MSTR 40    // kC: M row stride (halves): 80B rows, 16B-aligned, conflict-free
#define XSTR 72    // kC: X row stride (halves): 144B rows, 16B-aligned, conflict-free

__device__ __align__(16) __half g_qh[4 * HW * 16];  // [bs][p][16]  fp16
__device__ __align__(16) __half g_kh[4 * HW * 16];  // [bs][p][16]  fp16
__device__ __align__(16) __half g_xh[2 * 512 * HW]; // fp16 copy of x
__device__ __align__(16) __half g_u[2 * CCH * HW];  // [b][c][p]  fp16
__device__ __align__(16) __half g_Mh[CCH * 512];    // fused M, fp16
__device__ __align__(16) float g_bu[CCH];

__device__ __forceinline__ void mma16(float* c, const uint32_t* a,
                                      uint32_t b0, uint32_t b1) {
    asm volatile(
        "mma.sync.aligned.m16n8k16.row.col.f32.f16.f16.f32 "
        "{%0,%1,%2,%3}, {%4,%5,%6,%7}, {%8,%9}, {%0,%1,%2,%3};"
        : "+f"(c[0]), "+f"(c[1]), "+f"(c[2]), "+f"(c[3])
        : "r"(a[0]), "r"(a[1]), "r"(a[2]), "r"(a[3]), "r"(b0), "r"(b1));
}
__device__ __forceinline__ void ldsm4(uint32_t* r, uint32_t saddr) {
    asm volatile("ldmatrix.sync.aligned.m8n8.x4.shared.b16 {%0,%1,%2,%3}, [%4];"
                 : "=r"(r[0]), "=r"(r[1]), "=r"(r[2]), "=r"(r[3]) : "r"(saddr));
}
__device__ __forceinline__ void ldsm4t(uint32_t* r, uint32_t saddr) {
    asm volatile("ldmatrix.sync.aligned.m8n8.x4.trans.shared.b16 {%0,%1,%2,%3}, [%4];"
                 : "=r"(r[0]), "=r"(r[1]), "=r"(r[2]), "=r"(r[3]) : "r"(saddr));
}
__device__ __forceinline__ uint32_t s2u(const void* p) {
    uint32_t a;
    asm("{ .reg .u64 t; cvta.to.shared.u64 t, %1; cvt.u32.u64 %0, t; }"
        : "=r"(a) : "l"(p));
    return a;
}
__device__ __forceinline__ void cp16(uint32_t s, const void* g) {
    asm volatile("cp.async.cg.shared.global [%0], [%1], 16;" :: "r"(s), "l"(g));
}
#define CP_COMMIT() asm volatile("cp.async.commit_group;" ::: "memory")
#define CP_WAIT1()  asm volatile("cp.async.wait_group 1;" ::: "memory")

// ---------------------------------------------------------------------------
// Kernel AB (fused, independent halves):
//  blocks [0,64):   kA — M = [Wpt1*Wv | Wpt2*Wv] -> fp16 g_Mh (+ fused bias)
//  blocks [64,128): kB — q,k projections -> fp16; x -> fp16 g_xh
// ---------------------------------------------------------------------------
__global__ void __launch_bounds__(256) kAB(const float* __restrict__ Wpt,
                                           const float* __restrict__ Wv,
                                           const float* __restrict__ bv,
                                           const float* __restrict__ x,
                                           const float* __restrict__ Wq,
                                           const float* __restrict__ bq,
                                           const float* __restrict__ Wk,
                                           const float* __restrict__ bk) {
    __shared__ __align__(16) float pool[2 * 16 * 256];  // 32 KB
    int t = threadIdx.x;
    int bid = blockIdx.x;

    if (bid < 64) {
        // ----- kA: 32d x 64e tile, K=256 -----
        float* As = pool;             // [16][32]
        float* Bs = pool + 16 * 32;   // [16][64]
        int tx = t & 15, ty = t >> 4;
        int eb = (bid & 7) * 64, db = (bid >> 3) * 32;
        int half = eb >> 8, ebl = eb & 255;
        float acc[2][4];
#pragma unroll
        for (int i = 0; i < 2; ++i)
#pragma unroll
            for (int j = 0; j < 4; ++j) acc[i][j] = 0.f;

        for (int m0 = 0; m0 < 256; m0 += 16) {
            float4 av = make_float4(0.f, 0.f, 0.f, 0.f);
            int ar = t >> 2, ac4 = (t & 3) * 4;
            if (t < 128)
                av = *(const float4*)&Wpt[(db + ar) * 512 + half * 256 + m0 + ac4];
            int rb = t >> 4, p4 = (t & 15) * 4;
            float4 bv4 = *(const float4*)&Wv[(m0 + rb) * 256 + ebl + p4];
            __syncthreads();
            if (t < 128) {
                As[(ac4 + 0) * 32 + ar] = av.x;
                As[(ac4 + 1) * 32 + ar] = av.y;
                As[(ac4 + 2) * 32 + ar] = av.z;
                As[(ac4 + 3) * 32 + ar] = av.w;
            }
            *(float4*)&Bs[rb * 64 + p4] = bv4;
            __syncthreads();
#pragma unroll
            for (int e = 0; e < 16; ++e) {
                float a0 = As[e * 32 + ty * 2];
                float a1 = As[e * 32 + ty * 2 + 1];
                float4 bb = *(const float4*)&Bs[e * 64 + tx * 4];
                acc[0][0] = fmaf(a0, bb.x, acc[0][0]);
                acc[0][1] = fmaf(a0, bb.y, acc[0][1]);
                acc[0][2] = fmaf(a0, bb.z, acc[0][2]);
                acc[0][3] = fmaf(a0, bb.w, acc[0][3]);
                acc[1][0] = fmaf(a1, bb.x, acc[1][0]);
                acc[1][1] = fmaf(a1, bb.y, acc[1][1]);
                acc[1][2] = fmaf(a1, bb.z, acc[1][2]);
                acc[1][3] = fmaf(a1, bb.w, acc[1][3]);
            }
        }
#pragma unroll
        for (int dd = 0; dd < 2; ++dd) {
            int d = db + ty * 2 + dd;
            __half2* mp = (__half2*)&g_Mh[d * 512 + eb + tx * 4];
            mp[0] = __floats2half2_rn(acc[dd][0], acc[dd][1]);
            mp[1] = __floats2half2_rn(acc[dd][2], acc[dd][3]);
        }
        if ((bid & 7) == 0) {   // fused bias for this d-tile
            int d = db + (t >> 3);
            int l = t & 7;
            float bacc = 0.f;
#pragma unroll 8
            for (int j = 0; j < 32; ++j) {
                int m = l + 8 * j;
                bacc = fmaf(Wpt[d * 512 + m] + Wpt[d * 512 + 256 + m], bv[m], bacc);
            }
            bacc += __shfl_down_sync(0xffffffffu, bacc, 4, 8);
            bacc += __shfl_down_sync(0xffffffffu, bacc, 2, 8);
            bacc += __shfl_down_sync(0xffffffffu, bacc, 1, 8);
            if (l == 0) g_bu[d] = bacc;
        }
    } else {
        // ----- kB: 256 p-positions per block -----
        float* wq = pool;             // [16][256]
        float* wk = pool + 16 * 256;  // [16][256]
        for (int i = t; i < 16 * 256; i += 256) { wq[i] = Wq[i]; wk[i] = Wk[i]; }
        __syncthreads();
        int id2 = bid - 64;           // 0..63
        int b = id2 >> 5, s = (id2 >> 4) & 1, pblk = id2 & 15;
        int p = pblk * 256 + t;
        const float* xp = x + ((size_t)b * 512 + s * 256) * HW + p;
        __half* xhp = g_xh + ((size_t)b * 512 + s * 256) * HW + p;
        float qa[16], ka[16];
#pragma unroll
        for (int d = 0; d < 16; ++d) { qa[d] = bq[d]; ka[d] = bk[d]; }
#pragma unroll 4
        for (int c = 0; c < 256; ++c) {
            float xv = xp[(size_t)c * HW];
            xhp[(size_t)c * HW] = __float2half_rn(xv);
#pragma unroll
            for (int d = 0; d < 16; ++d) {
                qa[d] = fmaf(wq[d * 256 + c], xv, qa[d]);
                ka[d] = fmaf(wk[d * 256 + c], xv, ka[d]);
            }
        }
        __half* qdst = g_qh + ((size_t)(b * 2 + s) * HW + p) * 16;
        __half* kdst = g_kh + ((size_t)(b * 2 + s) * HW + p) * 16;
#pragma unroll
        for (int v = 0; v < 4; ++v) {
            *(__half2*)&qdst[v*4+0] = __floats2half2_rn(qa[v*4+0], qa[v*4+1]);
            *(__half2*)&qdst[v*4+2] = __floats2half2_rn(qa[v*4+2], qa[v*4+3]);
            *(__half2*)&kdst[v*4+0] = __floats2half2_rn(ka[v*4+0], ka[v*4+1]);
            *(__half2*)&kdst[v*4+2] = __floats2half2_rn(ka[v*4+2], ka[v*4+3]);
        }
    }
}

// ---------------------------------------------------------------------------
// Kernel C: u = M @ x + bu via fp16 mma.sync, cp.async triple-buffered.
// grid (64 p x 64, 2 c x 128, 2 b) = 256 CTAs, 256 threads.
// K=512 in 16 stages of 32. Warp tile 32c x 32p. (R15 version)
// ---------------------------------------------------------------------------
__global__ void __launch_bounds__(256) kC_u() {
    __shared__ __align__(16) __half Ms[3][128 * MSTR];  // 128c x 32k
    __shared__ __align__(16) __half Xs[3][32 * XSTR];   // 32k x 64p
    int t = threadIdx.x, w = t >> 5, lane = t & 31;
    int g = lane >> 2, tig = lane & 3;
    int pb = blockIdx.x * 64, cb = blockIdx.y * 128, b = blockIdx.z;
    int wc = w >> 1, wp = w & 1;

    const __half* mg = g_Mh + (size_t)cb * 512;
    const __half* xg = g_xh + (size_t)b * 512 * HW + pb;

    auto load_t = [&](int k) {
        int k0 = k * 32;
#pragma unroll
        for (int q = 0; q < 2; ++q) {
            int id = t + 256 * q;
            int row = id >> 2, c8 = (id & 3) * 8;
            cp16(s2u(&Ms[k % 3][row * MSTR + c8]),
                 mg + (size_t)row * 512 + k0 + c8);
        }
        int xr = t >> 3, xc8 = (t & 7) * 8;
        cp16(s2u(&Xs[k % 3][xr * XSTR + xc8]),
             xg + (size_t)(k0 + xr) * HW + xc8);
    };

    int lrow = (lane & 7) + ((lane >> 3) & 1) * 8;
    int lc8 = (lane >> 4) * 8;
    uint32_t ms_b = s2u(&Ms[0][0]);
    uint32_t xs_b = s2u(&Xs[0][0]);

    float O[2][4][4];
#pragma unroll
    for (int mb = 0; mb < 2; ++mb)
#pragma unroll
        for (int nb = 0; nb < 4; ++nb)
#pragma unroll
            for (int v = 0; v < 4; ++v) O[mb][nb][v] = 0.f;

    load_t(0); CP_COMMIT();
    load_t(1); CP_COMMIT();
    CP_WAIT1();
    __syncthreads();

    for (int k = 0; k < 16; ++k) {
        if (k + 2 < 16) load_t(k + 2);
        CP_COMMIT();
        int buf = k % 3;
        uint32_t msb = ms_b + (uint32_t)(buf * (128 * MSTR * 2));
        uint32_t xsb = xs_b + (uint32_t)(buf * (32 * XSTR * 2));
#pragma unroll
        for (int ksub = 0; ksub < 2; ++ksub) {
            uint32_t am[2][4];
            ldsm4(am[0], msb +
                  (uint32_t)(((wc * 32 + lrow) * MSTR + ksub * 16 + lc8) * 2));
            ldsm4(am[1], msb +
                  (uint32_t)(((wc * 32 + 16 + lrow) * MSTR + ksub * 16 + lc8) * 2));
#pragma unroll
            for (int nbp = 0; nbp < 2; ++nbp) {
                uint32_t bm[4];
                ldsm4t(bm, xsb + (uint32_t)(((ksub * 16 + lrow) * XSTR +
                                             wp * 32 + nbp * 16 + lc8) * 2));
                mma16(O[0][2 * nbp],     am[0], bm[0], bm[1]);
                mma16(O[0][2 * nbp + 1], am[0], bm[2], bm[3]);
                mma16(O[1][2 * nbp],     am[1], bm[0], bm[1]);
                mma16(O[1][2 * nbp + 1], am[1], bm[2], bm[3]);
            }
        }
        CP_WAIT1();
        __syncthreads();
    }

#pragma unroll
    for (int mb = 0; mb < 2; ++mb) {
        int c0 = cb + wc * 32 + mb * 16 + g;
        int c1 = c0 + 8;
        float bu0 = g_bu[c0], bu1 = g_bu[c1];
        __half* u0p = g_u + (size_t)(b * CCH + c0) * HW;
        __half* u1p = g_u + (size_t)(b * CCH + c1) * HW;
#pragma unroll
        for (int nb = 0; nb < 4; ++nb) {
            int p = pb + wp * 32 + nb * 8 + 2 * tig;
            *(__half2*)&u0p[p] = __floats2half2_rn(O[mb][nb][0] + bu0,
                                                   O[mb][nb][1] + bu0);
            *(__half2*)&u1p[p] = __floats2half2_rn(O[mb][nb][2] + bu1,
                                                   O[mb][nb][3] + bu1);
        }
    }
}

// ---------------------------------------------------------------------------
// Kernel D: fp16 flash attention, BALANCED MMA1 (all 16 warps, each tile).
// grid (32 ib, 4 bs) = 128 CTAs, 512 threads (16 warps).
// MMA1 warp tile: 16i x 32j  (i-block w&7, j-half w>>3).
// MMA2 warp tile: 32c x 64i  (cb2=(w>>1)*32, ih=(w&1)*64).
// l partials: jh=0 -> LsA, jh=1 -> LsB; combined at end.
// ---------------------------------------------------------------------------
__global__ void __launch_bounds__(512, 1) kD_attn(const float* __restrict__ x,
                                                  const float* __restrict__ bpt,
                                                  const float* __restrict__ gamma,
                                                  float* __restrict__ out) {
    extern __shared__ __align__(16) char dsm[];
    uint32_t u_b = s2u(dsm);                    // 3 U buffers
    __half* Ps = (__half*)(dsm + 3 * USZB);     // 2 P buffers
    float* LsA = (float*)(dsm + 3 * USZB + 2 * PSZB);
    float* LsB = LsA + 128;
    uint32_t ps_b = s2u(Ps);

    int t = threadIdx.x, w = t >> 5, lane = t & 31;
    int g = lane >> 2, tig = lane & 3;
    int ib = blockIdx.x, bs = blockIdx.y;
    int b = bs >> 1, s = bs & 1;
    int i0 = ib * 128;
    int wr = w & 7;            // MMA1 i-block
    int jh = w >> 3;           // MMA1 j-half (0/1)
    int cb2 = (w >> 1) * 32;   // MMA2 c-block
    int ih  = (w & 1) * 64;    // MMA2 i-half

    // persistent Q fragment (fp16 A-frag for rows [wr*16, wr*16+16))
    uint32_t qa16[4];
    {
        const __half* qp = g_qh + ((size_t)bs * HW + i0 + wr * 16) * 16;
        qa16[0] = *(const uint32_t*)&qp[g * 16 + 2 * tig];
        qa16[1] = *(const uint32_t*)&qp[(g + 8) * 16 + 2 * tig];
        qa16[2] = *(const uint32_t*)&qp[g * 16 + 8 + 2 * tig];
        qa16[3] = *(const uint32_t*)&qp[(g + 8) * 16 + 8 + 2 * tig];
    }

    uint32_t lm_p = ps_b +
        (uint32_t)((ih + ((lane >> 4) << 3) + (lane & 7)) * PSTRH * 2) +
        ((lane & 8) ? 16u : 0u);
    int ur = (lane & 7) + (((lane >> 3) & 1) << 3);
    int uc8 = (lane >> 4) << 3;
    uint32_t lm_u = u_b + (uint32_t)(((cb2 + ur) * USTRH + uc8) * 2);

    float O[2][8][4];
#pragma unroll
    for (int mb = 0; mb < 2; ++mb)
#pragma unroll
        for (int nb = 0; nb < 8; ++nb)
#pragma unroll
            for (int v = 0; v < 4; ++v) O[mb][nb][v] = 0.f;
    float lsum0 = 0.f, lsum1 = 0.f;

    const __half* kh = g_kh + (size_t)bs * HW * 16;
    const __half* uglob = g_u + (size_t)b * CCH * HW;

    auto load_u = [&](int n) {
        int j0 = n * 64;
        uint32_t dst = u_b + (uint32_t)((n % 3) * USZB);
        const __half* us = uglob + j0;
#pragma unroll
        for (int q = 0; q < 4; ++q) {
            int chunk = t + 512 * q;
            int r = chunk >> 3, c8 = (chunk & 7) * 8;
            cp16(dst + (uint32_t)((r * USTRH + c8) * 2), us + (size_t)r * HW + c8);
        }
    };

    // ---- MMA1 (all warps): S[16i x 32j] -> exp(s-EOFF) -> fp16 -> Ps[n&1] ----
    auto mma1_tile = [&](int n) {
        int j0 = n * 64 + jh * 32;
        __half* Pb = Ps + (n & 1) * (128 * PSTRH);
        float sa[4][4];
#pragma unroll
        for (int nb = 0; nb < 4; ++nb) {
            sa[nb][0] = sa[nb][1] = sa[nb][2] = sa[nb][3] = 0.f;
            const __half* kj = kh + (size_t)(j0 + nb * 8 + g) * 16;
            uint32_t kb0 = *(const uint32_t*)&kj[2 * tig];
            uint32_t kb1 = *(const uint32_t*)&kj[2 * tig + 8];
            mma16(sa[nb], qa16, kb0, kb1);
        }
#pragma unroll
        for (int nb = 0; nb < 4; ++nb) {
            float p0 = __expf(sa[nb][0] - EOFF);
            float p1 = __expf(sa[nb][1] - EOFF);
            float p2 = __expf(sa[nb][2] - EOFF);
            float p3 = __expf(sa[nb][3] - EOFF);
            __half2 h01 = __floats2half2_rn(p0, p1);
            __half2 h23 = __floats2half2_rn(p2, p3);
            float2 f01 = __half22float2(h01);
            float2 f23 = __half22float2(h23);
            lsum0 += f01.x + f01.y;
            lsum1 += f23.x + f23.y;
            int col = jh * 32 + nb * 8 + 2 * tig;
            *(__half2*)&Pb[(wr * 16 + g) * PSTRH + col] = h01;
            *(__half2*)&Pb[(wr * 16 + g + 8) * PSTRH + col] = h23;
        }
    };

    load_u(0); CP_COMMIT();
    load_u(1); CP_COMMIT();
    mma1_tile(0);
    CP_WAIT1();
    __syncthreads();

    for (int n = 0; n < 64; ++n) {
        if (n + 2 < 64) load_u(n + 2);
        CP_COMMIT();

        if (n + 1 < 64) mma1_tile(n + 1);

        // ---- MMA2: O[32c x 64i] += U * P(n)^T ----
        uint32_t lmp = lm_p + (uint32_t)((n & 1) * PSZB);
        uint32_t lmu = lm_u + (uint32_t)((n % 3) * USZB);
#pragma unroll
        for (int ks = 0; ks < 4; ++ks) {
            uint32_t ua0[4], ua1[4];
            ldsm4(ua0, lmu + (uint32_t)(ks * 32));
            ldsm4(ua1, lmu + (uint32_t)(16 * USTRH * 2 + ks * 32));
#pragma unroll
            for (int nbp = 0; nbp < 4; ++nbp) {
                uint32_t bm[4];
                ldsm4(bm, lmp + (uint32_t)(nbp * 16 * PSTRH * 2 + ks * 32));
                mma16(O[0][2 * nbp],     ua0, bm[0], bm[1]);
                mma16(O[1][2 * nbp],     ua1, bm[0], bm[1]);
                mma16(O[0][2 * nbp + 1], ua0, bm[2], bm[3]);
                mma16(O[1][2 * nbp + 1], ua1, bm[2], bm[3]);
            }
        }
        CP_WAIT1();
        __syncthreads();
    }

    // ---- l: quad-reduce, j-half partials, combine ----
    lsum0 += __shfl_xor_sync(0xffffffffu, lsum0, 1);
    lsum0 += __shfl_xor_sync(0xffffffffu, lsum0, 2);
    lsum1 += __shfl_xor_sync(0xffffffffu, lsum1, 1);
    lsum1 += __shfl_xor_sync(0xffffffffu, lsum1, 2);
    if (tig == 0) {
        float* Lp = (jh == 0) ? LsA : LsB;
        Lp[wr * 16 + g] = lsum0;
        Lp[wr * 16 + g + 8] = lsum1;
    }
    __syncthreads();
    if (t < 128) LsA[t] = 1.f / (LsA[t] + LsB[t]);
    __syncthreads();

    // ---- epilogue: out = gamma*(O/l + bpt) + x ----
    float gm = gamma[0];
#pragma unroll
    for (int mb = 0; mb < 2; ++mb) {
        int cA = cb2 + mb * 16 + g;
        int cB = cA + 8;
        float biasA = bpt[cA], biasB = bpt[cB];
        size_t baseA = ((size_t)b * 512 + s * 256 + cA) * HW + i0 + ih;
        size_t baseB = ((size_t)b * 512 + s * 256 + cB) * HW + i0 + ih;
#pragma unroll
        for (int nb = 0; nb < 8; ++nb) {
            int i = nb * 8 + 2 * tig;
            float il0 = LsA[ih + i], il1 = LsA[ih + i + 1];
            float2 xa = *(const float2*)&x[baseA + i];
            float2 xb = *(const float2*)&x[baseB + i];
            float2 oa, ob;
            oa.x = fmaf(gm, fmaf(O[mb][nb][0], il0, biasA), xa.x);
            oa.y = fmaf(gm, fmaf(O[mb][nb][1], il1, biasA), xa.y);
            ob.x = fmaf(gm, fmaf(O[mb][nb][2], il0, biasB), xb.x);
            ob.y = fmaf(gm, fmaf(O[mb][nb][3], il1, biasB), xb.y);
            *(float2*)&out[baseA + i] = oa;
            *(float2*)&out[baseB + i] = ob;
        }
    }
}

#define KD_SMEM (3 * USZB + 2 * PSZB + 256 * 4)

// ---------------------------------------------------------------------------
extern "C" void kernel_launch(void* const* d_in, const int* in_sizes, int n_in,
                              void* d_out, int out_size) {
    const float* x     = (const float*)d_in[0];
    const float* Wq    = (const float*)d_in[1];
    const float* bq    = (const float*)d_in[2];
    const float* Wk    = (const float*)d_in[3];
    const float* bk    = (const float*)d_in[4];
    const float* Wv    = (const float*)d_in[5];
    const float* bv    = (const float*)d_in[6];
    const float* Wpt   = (const float*)d_in[7];
    const float* bpt   = (const float*)d_in[8];
    const float* gamma = (const float*)d_in[9];
    float* out = (float*)d_out;

    static bool attr_done = false;
    if (!attr_done) {
        cudaFuncSetAttribute(kD_attn, cudaFuncAttributeMaxDynamicSharedMemorySize,
                             KD_SMEM);
        attr_done = true;
    }

    kAB<<<128, 256>>>(Wpt, Wv, bv, x, Wq, bq, Wk, bk);
    kC_u<<<dim3(64, 2, 2), 256>>>();
    kD_attn<<<dim3(32, 4), 512, KD_SMEM>>>(x, bpt, gamma, out);
}

// round 17
// speedup vs baseline: 1.0676x; 1.0676x over previous
#include <cuda_runtime.h>
#include <cuda_fp16.h>
#include <math.h>
#include <stdint.h>

// Shapes: B=2, C=256, H=W=64 -> HW=4096, DQ=16, x has 2C=512 channels.
#define HW 4096
#define CCH 256
#define PSTRH 72   // P smem row stride (halves): banks 4r+c, conflict-free
#define USTRH 72   // U smem row stride (halves)
#define EOFF 8.0f  // uniform logit offset (cancels in O/l)
#define USZB (256 * USTRH * 2)   // one U buffer, bytes (36864)
#define PSZB (128 * PSTRH * 2)   // one P buffer, bytes (18432)
#define MSTR 40    // kC: M row stride (halves): 80B rows, 16B-aligned, conflict-free
#define XSTR 72    // kC: X row stride (halves): 144B rows, 16B-aligned, conflict-free

__device__ __align__(16) __half g_qh[4 * HW * 16];  // [bs][p][16]  fp16
__device__ __align__(16) __half g_kh[4 * HW * 16];  // [bs][p][16]  fp16
__device__ __align__(16) __half g_xh[2 * 512 * HW]; // fp16 copy of x
__device__ __align__(16) __half g_u[2 * CCH * HW];  // [b][c][p]  fp16
__device__ __align__(16) __half g_Mh[CCH * 512];    // fused M, fp16
__device__ __align__(16) float g_bu[CCH];

__device__ __forceinline__ void mma16(float* c, const uint32_t* a,
                                      uint32_t b0, uint32_t b1) {
    asm volatile(
        "mma.sync.aligned.m16n8k16.row.col.f32.f16.f16.f32 "
        "{%0,%1,%2,%3}, {%4,%5,%6,%7}, {%8,%9}, {%0,%1,%2,%3};"
        : "+f"(c[0]), "+f"(c[1]), "+f"(c[2]), "+f"(c[3])
        : "r"(a[0]), "r"(a[1]), "r"(a[2]), "r"(a[3]), "r"(b0), "r"(b1));
}
__device__ __forceinline__ void ldsm4(uint32_t* r, uint32_t saddr) {
    asm volatile("ldmatrix.sync.aligned.m8n8.x4.shared.b16 {%0,%1,%2,%3}, [%4];"
                 : "=r"(r[0]), "=r"(r[1]), "=r"(r[2]), "=r"(r[3]) : "r"(saddr));
}
__device__ __forceinline__ void ldsm4t(uint32_t* r, uint32_t saddr) {
    asm volatile("ldmatrix.sync.aligned.m8n8.x4.trans.shared.b16 {%0,%1,%2,%3}, [%4];"
                 : "=r"(r[0]), "=r"(r[1]), "=r"(r[2]), "=r"(r[3]) : "r"(saddr));
}
__device__ __forceinline__ uint32_t s2u(const void* p) {
    uint32_t a;
    asm("{ .reg .u64 t; cvta.to.shared.u64 t, %1; cvt.u32.u64 %0, t; }"
        : "=r"(a) : "l"(p));
    return a;
}
__device__ __forceinline__ void cp16(uint32_t s, const void* g) {
    asm volatile("cp.async.cg.shared.global [%0], [%1], 16;" :: "r"(s), "l"(g));
}
#define CP_COMMIT() asm volatile("cp.async.commit_group;" ::: "memory")
#define CP_WAIT1()  asm volatile("cp.async.wait_group 1;" ::: "memory")

// ---------------------------------------------------------------------------
// Kernel A: M = [Wpt1*Wv | Wpt2*Wv] tiled GEMM -> fp16 g_Mh, bias fused.
// grid (8 e-tiles x 64, 8 d-tiles x 32) = 64 CTAs, 256 threads. (R15 version)
// ---------------------------------------------------------------------------
__global__ void __launch_bounds__(256) kA_fuse(const float* __restrict__ Wpt,
                                               const float* __restrict__ Wv,
                                               const float* __restrict__ bv) {
    __shared__ __align__(16) float As[16 * 32];
    __shared__ __align__(16) float Bs[16 * 64];
    int t = threadIdx.x, tx = t & 15, ty = t >> 4;
    int eb = blockIdx.x * 64, db = blockIdx.y * 32;
    int half = eb >> 8, ebl = eb & 255;
    float acc[2][4];
#pragma unroll
    for (int i = 0; i < 2; ++i)
#pragma unroll
        for (int j = 0; j < 4; ++j) acc[i][j] = 0.f;

    for (int m0 = 0; m0 < 256; m0 += 16) {
        float4 av = make_float4(0.f, 0.f, 0.f, 0.f);
        int ar = t >> 2, ac4 = (t & 3) * 4;
        if (t < 128)
            av = *(const float4*)&Wpt[(db + ar) * 512 + half * 256 + m0 + ac4];
        int rb = t >> 4, p4 = (t & 15) * 4;
        float4 bv4 = *(const float4*)&Wv[(m0 + rb) * 256 + ebl + p4];
        __syncthreads();
        if (t < 128) {
            As[(ac4 + 0) * 32 + ar] = av.x;
            As[(ac4 + 1) * 32 + ar] = av.y;
            As[(ac4 + 2) * 32 + ar] = av.z;
            As[(ac4 + 3) * 32 + ar] = av.w;
        }
        *(float4*)&Bs[rb * 64 + p4] = bv4;
        __syncthreads();
#pragma unroll
        for (int e = 0; e < 16; ++e) {
            float a0 = As[e * 32 + ty * 2];
            float a1 = As[e * 32 + ty * 2 + 1];
            float4 bb = *(const float4*)&Bs[e * 64 + tx * 4];
            acc[0][0] = fmaf(a0, bb.x, acc[0][0]);
            acc[0][1] = fmaf(a0, bb.y, acc[0][1]);
            acc[0][2] = fmaf(a0, bb.z, acc[0][2]);
            acc[0][3] = fmaf(a0, bb.w, acc[0][3]);
            acc[1][0] = fmaf(a1, bb.x, acc[1][0]);
            acc[1][1] = fmaf(a1, bb.y, acc[1][1]);
            acc[1][2] = fmaf(a1, bb.z, acc[1][2]);
            acc[1][3] = fmaf(a1, bb.w, acc[1][3]);
        }
    }
#pragma unroll
    for (int dd = 0; dd < 2; ++dd) {
        int d = db + ty * 2 + dd;
        __half2* mp = (__half2*)&g_Mh[d * 512 + eb + tx * 4];
        mp[0] = __floats2half2_rn(acc[dd][0], acc[dd][1]);
        mp[1] = __floats2half2_rn(acc[dd][2], acc[dd][3]);
    }
    if (blockIdx.x == 0) {
        int d = db + (t >> 3);
        int l = t & 7;
        float bacc = 0.f;
#pragma unroll 8
        for (int j = 0; j < 32; ++j) {
            int m = l + 8 * j;
            bacc = fmaf(Wpt[d * 512 + m] + Wpt[d * 512 + 256 + m], bv[m], bacc);
        }
        bacc += __shfl_down_sync(0xffffffffu, bacc, 4, 8);
        bacc += __shfl_down_sync(0xffffffffu, bacc, 2, 8);
        bacc += __shfl_down_sync(0xffffffffu, bacc, 1, 8);
        if (l == 0) g_bu[d] = bacc;
    }
}

// ---------------------------------------------------------------------------
// Kernel B: q,k projections -> fp16 [bs][p][16]; also x -> fp16 g_xh.
// (R15 version: 128 threads, 128 blocks)
// ---------------------------------------------------------------------------
__global__ void __launch_bounds__(128) kB_qk(const float* __restrict__ x,
                                             const float* __restrict__ Wq,
                                             const float* __restrict__ bq,
                                             const float* __restrict__ Wk,
                                             const float* __restrict__ bk) {
    __shared__ float wq[16 * 256];
    __shared__ float wk[16 * 256];
    int t = threadIdx.x;
    for (int i = t; i < 16 * 256; i += 128) { wq[i] = Wq[i]; wk[i] = Wk[i]; }
    __syncthreads();
    int p = blockIdx.x * 128 + t;
    int s = blockIdx.y, b = blockIdx.z;
    const float* xp = x + ((size_t)b * 512 + s * 256) * HW + p;
    __half* xhp = g_xh + ((size_t)b * 512 + s * 256) * HW + p;
    float qa[16], ka[16];
#pragma unroll
    for (int d = 0; d < 16; ++d) { qa[d] = bq[d]; ka[d] = bk[d]; }
#pragma unroll 4
    for (int c = 0; c < 256; ++c) {
        float xv = xp[(size_t)c * HW];
        xhp[(size_t)c * HW] = __float2half_rn(xv);
#pragma unroll
        for (int d = 0; d < 16; ++d) {
            qa[d] = fmaf(wq[d * 256 + c], xv, qa[d]);
            ka[d] = fmaf(wk[d * 256 + c], xv, ka[d]);
        }
    }
    __half* qdst = g_qh + ((size_t)(b * 2 + s) * HW + p) * 16;
    __half* kdst = g_kh + ((size_t)(b * 2 + s) * HW + p) * 16;
#pragma unroll
    for (int v = 0; v < 4; ++v) {
        *(__half2*)&qdst[v*4+0] = __floats2half2_rn(qa[v*4+0], qa[v*4+1]);
        *(__half2*)&qdst[v*4+2] = __floats2half2_rn(qa[v*4+2], qa[v*4+3]);
        *(__half2*)&kdst[v*4+0] = __floats2half2_rn(ka[v*4+0], ka[v*4+1]);
        *(__half2*)&kdst[v*4+2] = __floats2half2_rn(ka[v*4+2], ka[v*4+3]);
    }
}

// ---------------------------------------------------------------------------
// Kernel C: u = M @ x + bu via fp16 mma.sync, cp.async triple-buffered.
// grid (64 p x 64, 2 c x 128, 2 b) = 256 CTAs, 256 threads. (R15 version)
// ---------------------------------------------------------------------------
__global__ void __launch_bounds__(256) kC_u() {
    __shared__ __align__(16) __half Ms[3][128 * MSTR];  // 128c x 32k
    __shared__ __align__(16) __half Xs[3][32 * XSTR];   // 32k x 64p
    int t = threadIdx.x, w = t >> 5, lane = t & 31;
    int g = lane >> 2, tig = lane & 3;
    int pb = blockIdx.x * 64, cb = blockIdx.y * 128, b = blockIdx.z;
    int wc = w >> 1, wp = w & 1;

    const __half* mg = g_Mh + (size_t)cb * 512;
    const __half* xg = g_xh + (size_t)b * 512 * HW + pb;

    auto load_t = [&](int k) {
        int k0 = k * 32;
#pragma unroll
        for (int q = 0; q < 2; ++q) {
            int id = t + 256 * q;
            int row = id >> 2, c8 = (id & 3) * 8;
            cp16(s2u(&Ms[k % 3][row * MSTR + c8]),
                 mg + (size_t)row * 512 + k0 + c8);
        }
        int xr = t >> 3, xc8 = (t & 7) * 8;
        cp16(s2u(&Xs[k % 3][xr * XSTR + xc8]),
             xg + (size_t)(k0 + xr) * HW + xc8);
    };

    int lrow = (lane & 7) + ((lane >> 3) & 1) * 8;
    int lc8 = (lane >> 4) * 8;
    uint32_t ms_b = s2u(&Ms[0][0]);
    uint32_t xs_b = s2u(&Xs[0][0]);

    float O[2][4][4];
#pragma unroll
    for (int mb = 0; mb < 2; ++mb)
#pragma unroll
        for (int nb = 0; nb < 4; ++nb)
#pragma unroll
            for (int v = 0; v < 4; ++v) O[mb][nb][v] = 0.f;

    load_t(0); CP_COMMIT();
    load_t(1); CP_COMMIT();
    CP_WAIT1();
    __syncthreads();

    for (int k = 0; k < 16; ++k) {
        if (k + 2 < 16) load_t(k + 2);
        CP_COMMIT();
        int buf = k % 3;
        uint32_t msb = ms_b + (uint32_t)(buf * (128 * MSTR * 2));
        uint32_t xsb = xs_b + (uint32_t)(buf * (32 * XSTR * 2));
#pragma unroll
        for (int ksub = 0; ksub < 2; ++ksub) {
            uint32_t am[2][4];
            ldsm4(am[0], msb +
                  (uint32_t)(((wc * 32 + lrow) * MSTR + ksub * 16 + lc8) * 2));
            ldsm4(am[1], msb +
                  (uint32_t)(((wc * 32 + 16 + lrow) * MSTR + ksub * 16 + lc8) * 2));
#pragma unroll
            for (int nbp = 0; nbp < 2; ++nbp) {
                uint32_t bm[4];
                ldsm4t(bm, xsb + (uint32_t)(((ksub * 16 + lrow) * XSTR +
                                             wp * 32 + nbp * 16 + lc8) * 2));
                mma16(O[0][2 * nbp],     am[0], bm[0], bm[1]);
                mma16(O[0][2 * nbp + 1], am[0], bm[2], bm[3]);
                mma16(O[1][2 * nbp],     am[1], bm[0], bm[1]);
                mma16(O[1][2 * nbp + 1], am[1], bm[2], bm[3]);
            }
        }
        CP_WAIT1();
        __syncthreads();
    }

#pragma unroll
    for (int mb = 0; mb < 2; ++mb) {
        int c0 = cb + wc * 32 + mb * 16 + g;
        int c1 = c0 + 8;
        float bu0 = g_bu[c0], bu1 = g_bu[c1];
        __half* u0p = g_u + (size_t)(b * CCH + c0) * HW;
        __half* u1p = g_u + (size_t)(b * CCH + c1) * HW;
#pragma unroll
        for (int nb = 0; nb < 4; ++nb) {
            int p = pb + wp * 32 + nb * 8 + 2 * tig;
            *(__half2*)&u0p[p] = __floats2half2_rn(O[mb][nb][0] + bu0,
                                                   O[mb][nb][1] + bu0);
            *(__half2*)&u1p[p] = __floats2half2_rn(O[mb][nb][2] + bu1,
                                                   O[mb][nb][3] + bu1);
        }
    }
}

// ---------------------------------------------------------------------------
// Kernel D: fp16 flash attention, BALANCED MMA1 (all 16 warps, each tile).
// grid (32 ib, 4 bs) = 128 CTAs, 512 threads. (R16 version — the win)
// MMA1 warp tile: 16i x 32j  (i-block w&7, j-half w>>3).
// MMA2 warp tile: 32c x 64i  (cb2=(w>>1)*32, ih=(w&1)*64).
// ---------------------------------------------------------------------------
__global__ void __launch_bounds__(512, 1) kD_attn(const float* __restrict__ x,
                                                  const float* __restrict__ bpt,
                                                  const float* __restrict__ gamma,
                                                  float* __restrict__ out) {
    extern __shared__ __align__(16) char dsm[];
    uint32_t u_b = s2u(dsm);                    // 3 U buffers
    __half* Ps = (__half*)(dsm + 3 * USZB);     // 2 P buffers
    float* LsA = (float*)(dsm + 3 * USZB + 2 * PSZB);
    float* LsB = LsA + 128;
    uint32_t ps_b = s2u(Ps);

    int t = threadIdx.x, w = t >> 5, lane = t & 31;
    int g = lane >> 2, tig = lane & 3;
    int ib = blockIdx.x, bs = blockIdx.y;
    int b = bs >> 1, s = bs & 1;
    int i0 = ib * 128;
    int wr = w & 7;            // MMA1 i-block
    int jh = w >> 3;           // MMA1 j-half (0/1)
    int cb2 = (w >> 1) * 32;   // MMA2 c-block
    int ih  = (w & 1) * 64;    // MMA2 i-half

    uint32_t qa16[4];
    {
        const __half* qp = g_qh + ((size_t)bs * HW + i0 + wr * 16) * 16;
        qa16[0] = *(const uint32_t*)&qp[g * 16 + 2 * tig];
        qa16[1] = *(const uint32_t*)&qp[(g + 8) * 16 + 2 * tig];
        qa16[2] = *(const uint32_t*)&qp[g * 16 + 8 + 2 * tig];
        qa16[3] = *(const uint32_t*)&qp[(g + 8) * 16 + 8 + 2 * tig];
    }

    uint32_t lm_p = ps_b +
        (uint32_t)((ih + ((lane >> 4) << 3) + (lane & 7)) * PSTRH * 2) +
        ((lane & 8) ? 16u : 0u);
    int ur = (lane & 7) + (((lane >> 3) & 1) << 3);
    int uc8 = (lane >> 4) << 3;
    uint32_t lm_u = u_b + (uint32_t)(((cb2 + ur) * USTRH + uc8) * 2);

    float O[2][8][4];
#pragma unroll
    for (int mb = 0; mb < 2; ++mb)
#pragma unroll
        for (int nb = 0; nb < 8; ++nb)
#pragma unroll
            for (int v = 0; v < 4; ++v) O[mb][nb][v] = 0.f;
    float lsum0 = 0.f, lsum1 = 0.f;

    const __half* kh = g_kh + (size_t)bs * HW * 16;
    const __half* uglob = g_u + (size_t)b * CCH * HW;

    auto load_u = [&](int n) {
        int j0 = n * 64;
        uint32_t dst = u_b + (uint32_t)((n % 3) * USZB);
        const __half* us = uglob + j0;
#pragma unroll
        for (int q = 0; q < 4; ++q) {
            int chunk = t + 512 * q;
            int r = chunk >> 3, c8 = (chunk & 7) * 8;
            cp16(dst + (uint32_t)((r * USTRH + c8) * 2), us + (size_t)r * HW + c8);
        }
    };

    auto mma1_tile = [&](int n) {
        int j0 = n * 64 + jh * 32;
        __half* Pb = Ps + (n & 1) * (128 * PSTRH);
        float sa[4][4];
#pragma unroll
        for (int nb = 0; nb < 4; ++nb) {
            sa[nb][0] = sa[nb][1] = sa[nb][2] = sa[nb][3] = 0.f;
            const __half* kj = kh + (size_t)(j0 + nb * 8 + g) * 16;
            uint32_t kb0 = *(const uint32_t*)&kj[2 * tig];
            uint32_t kb1 = *(const uint32_t*)&kj[2 * tig + 8];
            mma16(sa[nb], qa16, kb0, kb1);
        }
#pragma unroll
        for (int nb = 0; nb < 4; ++nb) {
            float p0 = __expf(sa[nb][0] - EOFF);
            float p1 = __expf(sa[nb][1] - EOFF);
            float p2 = __expf(sa[nb][2] - EOFF);
            float p3 = __expf(sa[nb][3] - EOFF);
            __half2 h01 = __floats2half2_rn(p0, p1);
            __half2 h23 = __floats2half2_rn(p2, p3);
            float2 f01 = __half22float2(h01);
            float2 f23 = __half22float2(h23);
            lsum0 += f01.x + f01.y;
            lsum1 += f23.x + f23.y;
            int col = jh * 32 + nb * 8 + 2 * tig;
            *(__half2*)&Pb[(wr * 16 + g) * PSTRH + col] = h01;
            *(__half2*)&Pb[(wr * 16 + g + 8) * PSTRH + col] = h23;
        }
    };

    load_u(0); CP_COMMIT();
    load_u(1); CP_COMMIT();
    mma1_tile(0);
    CP_WAIT1();
    __syncthreads();

    for (int n = 0; n < 64; ++n) {
        if (n + 2 < 64) load_u(n + 2);
        CP_COMMIT();

        if (n + 1 < 64) mma1_tile(n + 1);

        uint32_t lmp = lm_p + (uint32_t)((n & 1) * PSZB);
        uint32_t lmu = lm_u + (uint32_t)((n % 3) * USZB);
#pragma unroll
        for (int ks = 0; ks < 4; ++ks) {
            uint32_t ua0[4], ua1[4];
            ldsm4(ua0, lmu + (uint32_t)(ks * 32));
            ldsm4(ua1, lmu + (uint32_t)(16 * USTRH * 2 + ks * 32));
#pragma unroll
            for (int nbp = 0; nbp < 4; ++nbp) {
                uint32_t bm[4];
                ldsm4(bm, lmp + (uint32_t)(nbp * 16 * PSTRH * 2 + ks * 32));
                mma16(O[0][2 * nbp],     ua0, bm[0], bm[1]);
                mma16(O[1][2 * nbp],     ua1, bm[0], bm[1]);
                mma16(O[0][2 * nbp + 1], ua0, bm[2], bm[3]);
                mma16(O[1][2 * nbp + 1], ua1, bm[2], bm[3]);
            }
        }
        CP_WAIT1();
        __syncthreads();
    }

    lsum0 += __shfl_xor_sync(0xffffffffu, lsum0, 1);
    lsum0 += __shfl_xor_sync(0xffffffffu, lsum0, 2);
    lsum1 += __shfl_xor_sync(0xffffffffu, lsum1, 1);
    lsum1 += __shfl_xor_sync(0xffffffffu, lsum1, 2);
    if (tig == 0) {
        float* Lp = (jh == 0) ? LsA : LsB;
        Lp[wr * 16 + g] = lsum0;
        Lp[wr * 16 + g + 8] = lsum1;
    }
    __syncthreads();
    if (t < 128) LsA[t] = 1.f / (LsA[t] + LsB[t]);
    __syncthreads();

    float gm = gamma[0];
#pragma unroll
    for (int mb = 0; mb < 2; ++mb) {
        int cA = cb2 + mb * 16 + g;
        int cB = cA + 8;
        float biasA = bpt[cA], biasB = bpt[cB];
        size_t baseA = ((size_t)b * 512 + s * 256 + cA) * HW + i0 + ih;
        size_t baseB = ((size_t)b * 512 + s * 256 + cB) * HW + i0 + ih;
#pragma unroll
        for (int nb = 0; nb < 8; ++nb) {
            int i = nb * 8 + 2 * tig;
            float il0 = LsA[ih + i], il1 = LsA[ih + i + 1];
            float2 xa = *(const float2*)&x[baseA + i];
            float2 xb = *(const float2*)&x[baseB + i];
            float2 oa, ob;
            oa.x = fmaf(gm, fmaf(O[mb][nb][0], il0, biasA), xa.x);
            oa.y = fmaf(gm, fmaf(O[mb][nb][1], il1, biasA), xa.y);
            ob.x = fmaf(gm, fmaf(O[mb][nb][2], il0, biasB), xb.x);
            ob.y = fmaf(gm, fmaf(O[mb][nb][3], il1, biasB), xb.y);
            *(float2*)&out[baseA + i] = oa;
            *(float2*)&out[baseB + i] = ob;
        }
    }
}

#define KD_SMEM (3 * USZB + 2 * PSZB + 256 * 4)

// ---------------------------------------------------------------------------
extern "C" void kernel_launch(void* const* d_in, const int* in_sizes, int n_in,
                              void* d_out, int out_size) {
    const float* x     = (const float*)d_in[0];
    const float* Wq    = (const float*)d_in[1];
    const float* bq    = (const float*)d_in[2];
    const float* Wk    = (const float*)d_in[3];
    const float* bk    = (const float*)d_in[4];
    const float* Wv    = (const float*)d_in[5];
    const float* bv    = (const float*)d_in[6];
    const float* Wpt   = (const float*)d_in[7];
    const float* bpt   = (const float*)d_in[8];
    const float* gamma = (const float*)d_in[9];
    float* out = (float*)d_out;

    static bool attr_done = false;
    if (!attr_done) {
        cudaFuncSetAttribute(kD_attn, cudaFuncAttributeMaxDynamicSharedMemorySize,
                             KD_SMEM);
        attr_done = true;
    }

    kA_fuse<<<dim3(8, 8), 256>>>(Wpt, Wv, bv);
    kB_qk<<<dim3(32, 2, 2), 128>>>(x, Wq, bq, Wk, bk);
    kC_u<<<dim3(64, 2, 2), 256>>>();
    kD_attn<<<dim3(32, 4), 512, KD_SMEM>>>(x, bpt, gamma, out);
}